// round 8
// baseline (speedup 1.0000x reference)
#include <cuda_runtime.h>
#include <cstdint>

#define N_NODES 20000
#define N_EDGES 320000
#define F_IN   256
#define F_HID  512

// ---------------- device scratch (no allocs allowed) ----------------
__device__ float g_acc[N_NODES * F_IN];          // (1+eps)*x + segment_sum
__device__ float g_W1T_e[F_HID * F_IN];          // [n=512][k=256] tf32, k-permuted
__device__ float g_W2T_e[F_IN * F_HID];          // [n=256][k=512]
__device__ float g_W1T_n[F_HID * F_IN];
__device__ float g_W2T_n[F_IN * F_HID];

// ---------------- helpers ----------------
__device__ __forceinline__ uint32_t smem_u32(const void* p) {
    uint32_t a;
    asm("{ .reg .u64 t; cvta.to.shared.u64 t, %1; cvt.u32.u64 %0, t; }" : "=r"(a) : "l"(p));
    return a;
}
__device__ __forceinline__ float f2tf32(float x) {
    uint32_t o; asm("cvt.rna.tf32.f32 %0, %1;" : "=r"(o) : "f"(x));
    return __uint_as_float(o);
}
__device__ __forceinline__ float4 cvt4(float4 v) {
    v.x = f2tf32(v.x); v.y = f2tf32(v.y); v.z = f2tf32(v.z); v.w = f2tf32(v.w);
    return v;
}
// m16n8k8 tf32 mma: d += a * b
__device__ __forceinline__ void mma8(float* d, float a0, float a1, float a2, float a3,
                                     float b0, float b1) {
    asm volatile(
        "mma.sync.aligned.m16n8k8.row.col.f32.tf32.tf32.f32 "
        "{%0,%1,%2,%3}, {%4,%5,%6,%7}, {%8,%9}, {%0,%1,%2,%3};"
        : "+f"(d[0]), "+f"(d[1]), "+f"(d[2]), "+f"(d[3])
        : "r"(__float_as_uint(a0)), "r"(__float_as_uint(a1)),
          "r"(__float_as_uint(a2)), "r"(__float_as_uint(a3)),
          "r"(__float_as_uint(b0)), "r"(__float_as_uint(b1)));
}
__device__ __forceinline__ void cp16(uint32_t sdst, const void* gsrc) {
    asm volatile("cp.async.ca.shared.global [%0], [%1], 16;" :: "r"(sdst), "l"(gsrc) : "memory");
}
#define CP_COMMIT() asm volatile("cp.async.commit_group;" ::: "memory")
#define CP_WAIT0()  asm volatile("cp.async.wait_group 0;" ::: "memory")

// ---------------- misc kernels ----------------
__global__ void init_acc_kernel(const float* __restrict__ node_feat,
                                const float* __restrict__ eps) {
    const float s = 1.0f + eps[0];
    int i = blockIdx.x * blockDim.x + threadIdx.x;
    float4 v = reinterpret_cast<const float4*>(node_feat)[i];
    v.x *= s; v.y *= s; v.z *= s; v.w *= s;
    reinterpret_cast<float4*>(g_acc)[i] = v;
}

// out[n*K + k] = tf32(in[orig_k * N + n]), k permuted within 8-groups:
// position p holds orig (p&1) ? (p>>1)+4 : (p>>1)
__global__ void transpose_cvt_kernel(const float* __restrict__ in,
                                     float* __restrict__ out, int K, int N) {
    int idx = blockIdx.x * blockDim.x + threadIdx.x;
    if (idx >= K * N) return;
    int n = idx / K;
    int k = idx - n * K;
    int p = k & 7;
    int o = (p & 1) ? (p >> 1) + 4 : (p >> 1);
    out[idx] = f2tf32(in[((k & ~7) + o) * N + n]);
}

// ---------------- fused 2-layer MLP on mma.sync tf32 ----------------
// 128 rows/CTA, 256 threads (8 warps = 4 row x 2 col).
// SMEM (floats):  Xs [128][264]  @0       (33792)   264 % 32 == 8: conflict-free
//                 Hs [128][72]   @33792   (9216)
//                 Wb 2 x 6144    @43008   (12288)   W1 slice 64x40 / W2 slice 256x24
//                 b1s[512]       @55296
//                 b2s[256]       @55808   total 56064 floats = 224256 B
#define OFF_HS  33792
#define OFF_WB  43008
#define WB_STRIDE_B 24576u    /* 6144 floats * 4 */
#define OFF_B1  55296
#define OFF_B2  55808
#define SMEM_FLOATS 56064
#define SMEM_BYTES  (SMEM_FLOATS * 4)

template <bool EDGE>
__global__ void __launch_bounds__(256, 1)
gine_mma(const float* __restrict__ Xin,
         const float* __restrict__ W1T, const float* __restrict__ b1,
         const float* __restrict__ W2T, const float* __restrict__ b2,
         const float* __restrict__ node_feat,
         const int* __restrict__ src, const int* __restrict__ dst,
         float* __restrict__ out, int M_total) {
    extern __shared__ float sm[];
    float* Xs  = sm;
    float* Hs  = sm + OFF_HS;
    float* Wb  = sm + OFF_WB;
    float* b1s = sm + OFF_B1;
    float* b2s = sm + OFF_B2;
    const uint32_t wb_u32 = smem_u32(Wb);

    const int tid  = threadIdx.x;
    const int lane = tid & 31;
    const int grp  = lane >> 2;     // 0..7
    const int tig  = lane & 3;      // 0..3
    const int wid  = tid >> 5;
    const int wr   = wid & 3;       // rows wr*32..+31
    const int wc   = wid >> 2;      // 0..1
    const int m0   = blockIdx.x * 128;

    const float4* X4   = reinterpret_cast<const float4*>(Xin);
    const float4* W1T4 = reinterpret_cast<const float4*>(W1T);
    const float4* W2T4 = reinterpret_cast<const float4*>(W2T);

    // biases
    for (int i = tid; i < 512; i += 256) b1s[i] = b1[i];
    b2s[tid] = b2[tid];

    // stage X tile [128][256] -> tf32, k-permuted within 8-groups
    #pragma unroll
    for (int it = 0; it < 32; ++it) {
        int i = it * 256 + tid;
        int r = i >> 6, c4 = i & 63;
        int gr = m0 + r; if (gr >= M_total) gr = M_total - 1;
        float4 v = cvt4(X4[gr * 64 + c4]);
        // float4 covers orig k (c4&1? 4..7 : 0..3) of group c4>>1 -> stride-2 positions
        float* bp = Xs + r * 264 + (c4 >> 1) * 8 + (c4 & 1);
        bp[0] = v.x; bp[2] = v.y; bp[4] = v.z; bp[6] = v.w;
    }

    float acc2[2][16][4];
    #pragma unroll
    for (int mi = 0; mi < 2; ++mi)
        #pragma unroll
        for (int ni = 0; ni < 16; ++ni)
            #pragma unroll
            for (int q = 0; q < 4; ++q) acc2[mi][ni][q] = 0.f;

    // ---- staging helpers (cp.async into Wb[buf]) ----
    auto stage_w1 = [&](int hc, int kt, int buf) {
        #pragma unroll
        for (int it = 0; it < 2; ++it) {
            int i = it * 256 + tid;
            int r = i >> 3, g = i & 7;
            cp16(wb_u32 + (uint32_t)buf * WB_STRIDE_B + (uint32_t)(r * 40 + g * 4) * 4u,
                 W1T4 + (hc * 64 + r) * 64 + kt * 8 + g);
        }
    };
    auto stage_w2 = [&](int hc, int kt2, int buf) {
        #pragma unroll
        for (int it = 0; it < 4; ++it) {
            int i = it * 256 + tid;
            int r = i >> 2, g = i & 3;
            cp16(wb_u32 + (uint32_t)buf * WB_STRIDE_B + (uint32_t)(r * 24 + g * 4) * 4u,
                 W2T4 + r * 128 + hc * 16 + kt2 * 4 + g);
        }
    };

    // prologue: stage 0 = (hc0, W1 kt0) into buf 0
    stage_w1(0, 0, 0);
    CP_COMMIT();
    int cur = 0;   // stage index being computed; stage s lives in buf (s&1)

    const int rowA0 = (wr * 32 + grp) * 264;        // Xs row bases
    const int rowA1 = rowA0 + 8 * 264;
    const int rowH0 = (wr * 32 + grp) * 72;         // Hs row bases
    const int rowH1 = rowH0 + 8 * 72;

    for (int hc = 0; hc < 8; ++hc) {
        // ===== GEMM1: H chunk [128 x 64] =====
        float acc1[2][4][4];
        #pragma unroll
        for (int mi = 0; mi < 2; ++mi)
            #pragma unroll
            for (int ni = 0; ni < 4; ++ni)
                #pragma unroll
                for (int q = 0; q < 4; ++q) acc1[mi][ni][q] = 0.f;

        for (int kt = 0; kt < 8; ++kt) {
            CP_WAIT0();
            __syncthreads();
            if (kt < 7) stage_w1(hc, kt + 1, (cur + 1) & 1);
            else        stage_w2(hc, 0, (cur + 1) & 1);
            CP_COMMIT();
            const float* Wc = Wb + (cur & 1) * 6144;
            ++cur;
            #pragma unroll
            for (int k8 = 0; k8 < 4; ++k8) {
                const int kb = kt * 32 + k8 * 8 + 2 * tig;
                float2 fa00 = *reinterpret_cast<const float2*>(Xs + rowA0 + kb);
                float2 fa01 = *reinterpret_cast<const float2*>(Xs + rowA1 + kb);
                float2 fa10 = *reinterpret_cast<const float2*>(Xs + rowA0 + 16 * 264 + kb);
                float2 fa11 = *reinterpret_cast<const float2*>(Xs + rowA1 + 16 * 264 + kb);
                #pragma unroll
                for (int ni = 0; ni < 4; ++ni) {
                    const int nb = wc * 32 + ni * 8 + grp;
                    float2 fb = *reinterpret_cast<const float2*>(Wc + nb * 40 + k8 * 8 + 2 * tig);
                    mma8(acc1[0][ni], fa00.x, fa01.x, fa00.y, fa01.y, fb.x, fb.y);
                    mma8(acc1[1][ni], fa10.x, fa11.x, fa10.y, fa11.y, fb.x, fb.y);
                }
            }
        }
        // epilogue1: Hs = tf32(relu(acc1 + b1)), written k-permuted
        {
            const int p0 = (tig < 2) ? 4 * tig : 4 * tig - 7;
            #pragma unroll
            for (int mi = 0; mi < 2; ++mi)
                #pragma unroll
                for (int ni = 0; ni < 4; ++ni) {
                    const int colg = wc * 32 + ni * 8;
                    const int bcol = hc * 64 + colg + 2 * tig;
                    float bb0 = b1s[bcol], bb1 = b1s[bcol + 1];
                    float* h0 = Hs + rowH0 + mi * 16 * 72 + colg + p0;
                    float* h1 = Hs + rowH1 + mi * 16 * 72 + colg + p0;
                    h0[0] = f2tf32(fmaxf(acc1[mi][ni][0] + bb0, 0.f));
                    h0[2] = f2tf32(fmaxf(acc1[mi][ni][1] + bb1, 0.f));
                    h1[0] = f2tf32(fmaxf(acc1[mi][ni][2] + bb0, 0.f));
                    h1[2] = f2tf32(fmaxf(acc1[mi][ni][3] + bb1, 0.f));
                }
        }
        // ===== GEMM2 partial: acc2 += Hchunk @ W2T slice =====
        for (int kt2 = 0; kt2 < 4; ++kt2) {
            CP_WAIT0();
            __syncthreads();
            if (kt2 < 3)      stage_w2(hc, kt2 + 1, (cur + 1) & 1);
            else if (hc < 7)  stage_w1(hc + 1, 0, (cur + 1) & 1);
            CP_COMMIT();
            const float* Wc = Wb + (cur & 1) * 6144;
            ++cur;
            #pragma unroll
            for (int k8 = 0; k8 < 2; ++k8) {
                const int kb = kt2 * 16 + k8 * 8 + 2 * tig;
                float2 ha00 = *reinterpret_cast<const float2*>(Hs + rowH0 + kb);
                float2 ha01 = *reinterpret_cast<const float2*>(Hs + rowH1 + kb);
                float2 ha10 = *reinterpret_cast<const float2*>(Hs + rowH0 + 16 * 72 + kb);
                float2 ha11 = *reinterpret_cast<const float2*>(Hs + rowH1 + 16 * 72 + kb);
                #pragma unroll
                for (int ni = 0; ni < 16; ++ni) {
                    const int nb = wc * 128 + ni * 8 + grp;
                    float2 fb = *reinterpret_cast<const float2*>(Wc + nb * 24 + k8 * 8 + 2 * tig);
                    mma8(acc2[0][ni], ha00.x, ha01.x, ha00.y, ha01.y, fb.x, fb.y);
                    mma8(acc2[1][ni], ha10.x, ha11.x, ha10.y, ha11.y, fb.x, fb.y);
                }
            }
        }
    }

    // ===== final epilogue: restage acc2 -> Xs (orig n order) for coalescing =====
    __syncthreads();
    #pragma unroll
    for (int mi = 0; mi < 2; ++mi)
        #pragma unroll
        for (int ni = 0; ni < 16; ++ni) {
            int row = wr * 32 + mi * 16 + grp;
            int col = wc * 128 + ni * 8 + 2 * tig;
            Xs[row * 264 + col]           = acc2[mi][ni][0];
            Xs[row * 264 + col + 1]       = acc2[mi][ni][1];
            Xs[(row + 8) * 264 + col]     = acc2[mi][ni][2];
            Xs[(row + 8) * 264 + col + 1] = acc2[mi][ni][3];
        }
    __syncthreads();

    #pragma unroll 4
    for (int it = 0; it < 32; ++it) {
        int r  = it * 4 + (tid >> 6);
        int c4 = tid & 63;
        int gr = m0 + r;
        float4 v = *reinterpret_cast<float4*>(Xs + r * 264 + c4 * 4);
        float4 bb = *reinterpret_cast<float4*>(b2s + c4 * 4);
        v.x += bb.x; v.y += bb.y; v.z += bb.z; v.w += bb.w;
        if (EDGE) {
            int s = src[gr];
            int d = dst[gr];
            float4 nf = reinterpret_cast<const float4*>(node_feat)[s * 64 + c4];
            v.x = fmaxf(v.x + nf.x, 0.f);
            v.y = fmaxf(v.y + nf.y, 0.f);
            v.z = fmaxf(v.z + nf.z, 0.f);
            v.w = fmaxf(v.w + nf.w, 0.f);
            float* p = g_acc + (size_t)d * 256 + c4 * 4;
            asm volatile("red.global.add.v4.f32 [%0], {%1, %2, %3, %4};"
                         :: "l"(p), "f"(v.x), "f"(v.y), "f"(v.z), "f"(v.w)
                         : "memory");
        } else if (gr < M_total) {
            reinterpret_cast<float4*>(out)[gr * 64 + c4] = v;
        }
    }
}

// ---------------------------------------------------------------------------
extern "C" void kernel_launch(void* const* d_in, const int* in_sizes, int n_in,
                              void* d_out, int out_size) {
    const float* node_feat = (const float*)d_in[0];
    const float* edge_feat = (const float*)d_in[1];
    const int*   src       = (const int*)d_in[2];
    const int*   dst       = (const int*)d_in[3];
    const float* We1       = (const float*)d_in[4];
    const float* be1       = (const float*)d_in[5];
    const float* We2       = (const float*)d_in[6];
    const float* be2       = (const float*)d_in[7];
    const float* Wn1       = (const float*)d_in[8];
    const float* bn1       = (const float*)d_in[9];
    const float* Wn2       = (const float*)d_in[10];
    const float* bn2       = (const float*)d_in[11];
    const float* eps       = (const float*)d_in[12];
    float* out = (float*)d_out;

    cudaFuncSetAttribute(gine_mma<true>,
                         cudaFuncAttributeMaxDynamicSharedMemorySize, SMEM_BYTES);
    cudaFuncSetAttribute(gine_mma<false>,
                         cudaFuncAttributeMaxDynamicSharedMemorySize, SMEM_BYTES);

    float *W1Te, *W2Te, *W1Tn, *W2Tn, *accp;
    cudaGetSymbolAddress((void**)&W1Te, g_W1T_e);
    cudaGetSymbolAddress((void**)&W2Te, g_W2T_e);
    cudaGetSymbolAddress((void**)&W1Tn, g_W1T_n);
    cudaGetSymbolAddress((void**)&W2Tn, g_W2T_n);
    cudaGetSymbolAddress((void**)&accp, g_acc);

    // 1) acc = (1+eps)*node_feat
    init_acc_kernel<<<(N_NODES * F_IN / 4) / 256, 256>>>(node_feat, eps);

    // 2) weight transpose + tf32 convert + k-interleave permutation
    transpose_cvt_kernel<<<512, 256>>>(We1, W1Te, F_IN,  F_HID);
    transpose_cvt_kernel<<<512, 256>>>(We2, W2Te, F_HID, F_IN);
    transpose_cvt_kernel<<<512, 256>>>(Wn1, W1Tn, F_IN,  F_HID);
    transpose_cvt_kernel<<<512, 256>>>(Wn2, W2Tn, F_HID, F_IN);

    // 3) edge MLP + gather/relu/scatter-add  (2500 CTAs)
    gine_mma<true><<<N_EDGES / 128, 256, SMEM_BYTES>>>(
        edge_feat, W1Te, be1, W2Te, be2, node_feat, src, dst, nullptr, N_EDGES);

    // 4) node MLP on acc -> out              (157 CTAs)
    gine_mma<false><<<(N_NODES + 127) / 128, 256, SMEM_BYTES>>>(
        accp, W1Tn, bn1, W2Tn, bn2, nullptr, nullptr, nullptr, out, N_NODES);
}

// round 10
// speedup vs baseline: 1.8503x; 1.8503x over previous
#include <cuda_runtime.h>
#include <cuda_fp16.h>
#include <cstdint>

#define N_NODES 20000
#define N_EDGES 320000
#define F_IN   256
#define F_HID  512

// ---------------- device scratch (no allocs allowed) ----------------
__device__ float    g_acc[N_NODES * F_IN];        // (1+eps)*x + segment_sum
__device__ uint32_t g_W1h_e[F_HID * F_IN / 2];    // [n=512][128 words] half2, k-permuted
__device__ uint32_t g_W2h_e[F_IN * F_HID / 2];    // [n=256][256 words]
__device__ uint32_t g_W1h_n[F_HID * F_IN / 2];
__device__ uint32_t g_W2h_n[F_IN * F_HID / 2];

// ---------------- helpers ----------------
__device__ __forceinline__ uint32_t smem_u32(const void* p) {
    uint32_t a;
    asm("{ .reg .u64 t; cvta.to.shared.u64 t, %1; cvt.u32.u64 %0, t; }" : "=r"(a) : "l"(p));
    return a;
}
__device__ __forceinline__ uint32_t packh2(float a, float b) {
    __half2 h = __floats2half2_rn(a, b);
    return *reinterpret_cast<uint32_t*>(&h);
}
// m16n8k16 fp16 mma, f32 accum: d += a * b
__device__ __forceinline__ void mma16(float* d, uint32_t a0, uint32_t a1,
                                      uint32_t a2, uint32_t a3,
                                      uint32_t b0, uint32_t b1) {
    asm volatile(
        "mma.sync.aligned.m16n8k16.row.col.f32.f16.f16.f32 "
        "{%0,%1,%2,%3}, {%4,%5,%6,%7}, {%8,%9}, {%0,%1,%2,%3};"
        : "+f"(d[0]), "+f"(d[1]), "+f"(d[2]), "+f"(d[3])
        : "r"(a0), "r"(a1), "r"(a2), "r"(a3), "r"(b0), "r"(b1));
}
__device__ __forceinline__ void cp16(uint32_t sdst, const void* gsrc) {
    asm volatile("cp.async.ca.shared.global [%0], [%1], 16;" :: "r"(sdst), "l"(gsrc) : "memory");
}
#define CP_COMMIT() asm volatile("cp.async.commit_group;" ::: "memory")
#define CP_WAIT0()  asm volatile("cp.async.wait_group 0;" ::: "memory")

// word-level k-interleave: position p holds orig word (p&1)?(p>>1)+4:(p>>1);
// orig word j goes to position (j<4)? 2j : 2j-7
__device__ __forceinline__ int permpos(int j) { return (j < 4) ? 2 * j : 2 * j - 7; }

// ---------------- fused prep: init g_acc + convert all 4 weights ----------------
// blocks [0,5000): acc = (1+eps)*node_feat ; blocks [5000,6024): weights
__global__ void prep_kernel(const float* __restrict__ node_feat,
                            const float* __restrict__ eps,
                            const float* __restrict__ We1, const float* __restrict__ We2,
                            const float* __restrict__ Wn1, const float* __restrict__ Wn2) {
    int bid = blockIdx.x;
    int tid = threadIdx.x;
    if (bid < 5000) {
        const float s = 1.0f + eps[0];
        int i = bid * 256 + tid;
        float4 v = reinterpret_cast<const float4*>(node_feat)[i];
        v.x *= s; v.y *= s; v.z *= s; v.w *= s;
        reinterpret_cast<float4*>(g_acc)[i] = v;
        return;
    }
    int b2 = bid - 5000;
    int w = b2 >> 8;                       // 0..3
    int idx = (b2 & 255) * 256 + tid;      // 0..65535
    const float* in; uint32_t* out; int K, N;
    if      (w == 0) { in = We1; out = g_W1h_e; K = F_IN;  N = F_HID; }
    else if (w == 1) { in = We2; out = g_W2h_e; K = F_HID; N = F_IN;  }
    else if (w == 2) { in = Wn1; out = g_W1h_n; K = F_IN;  N = F_HID; }
    else             { in = Wn2; out = g_W2h_n; K = F_HID; N = F_IN;  }
    int KW = K >> 1;
    int n = idx / KW;
    int p = idx - n * KW;
    int j = p & 7;
    int o = (p & ~7) + ((j & 1) ? (j >> 1) + 4 : (j >> 1));   // orig word
    out[idx] = packh2(in[(2 * o) * N + n], in[(2 * o + 1) * N + n]);
}

__global__ void noop_kernel() {}

// ---------------- fused 2-layer MLP, fp16 mma ----------------
// 128 rows/CTA, 256 threads (8 warps = 4 row x 2 col).
// SMEM (uint32 words):
//   Xw [128][136]  @0      (17408)   136%32==8 -> conflict-free frag loads
//   Hw [128][40]   @17408  (5120)
//   Wb 2 x 6144    @22528  (12288)   W1 slice 64x24 / W2 slice 256x24
//   b1s[512] f32   @34816
//   b2s[256] f32   @35328   total 35584 words = 142336 B
#define OFF_HW  17408
#define OFF_WB  22528
#define WB_BYTES 24576u
#define OFF_B1  34816
#define OFF_B2  35328
#define SMEM_WORDS 35584
#define SMEM_BYTES (SMEM_WORDS * 4)

template <bool EDGE>
__global__ void __launch_bounds__(256, 1)
gine_mma(const float* __restrict__ Xin,
         const uint32_t* __restrict__ W1w, const float* __restrict__ b1,
         const uint32_t* __restrict__ W2w, const float* __restrict__ b2,
         const float* __restrict__ node_feat,
         const int* __restrict__ src, const int* __restrict__ dst,
         float* __restrict__ out, int M_total) {
    extern __shared__ uint32_t smw[];
    uint32_t* Xw  = smw;
    uint32_t* Hw  = smw + OFF_HW;
    uint32_t* Wb  = smw + OFF_WB;
    float*    b1s = reinterpret_cast<float*>(smw + OFF_B1);
    float*    b2s = reinterpret_cast<float*>(smw + OFF_B2);
    const uint32_t wb_u32 = smem_u32(Wb);

    const int tid  = threadIdx.x;
    const int lane = tid & 31;
    const int grp  = lane >> 2;     // 0..7
    const int tig  = lane & 3;      // 0..3
    const int wid  = tid >> 5;
    const int wr   = wid & 3;       // rows wr*32..+31
    const int wc   = wid >> 2;      // 0..1
    const int m0   = blockIdx.x * 128;

    const float4* X4 = reinterpret_cast<const float4*>(Xin);

    // biases
    for (int i = tid; i < 512; i += 256) b1s[i] = b1[i];
    b2s[tid] = b2[tid];

    // stage X tile [128][256] -> half2 words, k-permuted per 8-word group
    #pragma unroll
    for (int it = 0; it < 32; ++it) {
        int i = it * 256 + tid;
        int r = i >> 6, c4 = i & 63;
        int gr = m0 + r; if (gr >= M_total) gr = M_total - 1;
        float4 v = X4[gr * 64 + c4];
        int w0 = 2 * c4;                       // orig words w0, w0+1
        int base = w0 & ~7;
        int j0 = w0 & 7;
        uint32_t* rp = Xw + r * 136 + base;
        rp[permpos(j0)]     = packh2(v.x, v.y);
        rp[permpos(j0 + 1)] = packh2(v.z, v.w);
    }

    float acc2[2][16][4];
    #pragma unroll
    for (int mi = 0; mi < 2; ++mi)
        #pragma unroll
        for (int ni = 0; ni < 16; ++ni)
            #pragma unroll
            for (int q = 0; q < 4; ++q) acc2[mi][ni][q] = 0.f;

    // ---- staging (cp.async into Wb[buf], row stride 24 words) ----
    auto stage_w1 = [&](int hc, int kt, int buf) {
        int r = tid >> 2, g = tid & 3;         // 64 rows x 4 groups = 256
        cp16(wb_u32 + (uint32_t)buf * WB_BYTES + (uint32_t)(r * 24 + g * 4) * 4u,
             W1w + (hc * 64 + r) * 128 + kt * 16 + g * 4);
    };
    auto stage_w2 = [&](int hc, int kt2, int buf) {
        #pragma unroll
        for (int it = 0; it < 4; ++it) {
            int i = it * 256 + tid;
            int r = i >> 2, g = i & 3;         // 256 rows x 4 groups
            cp16(wb_u32 + (uint32_t)buf * WB_BYTES + (uint32_t)(r * 24 + g * 4) * 4u,
                 W2w + r * 256 + hc * 32 + kt2 * 16 + g * 4);
        }
    };

    stage_w1(0, 0, 0);
    CP_COMMIT();
    int cur = 0;

    const int rowA0 = (wr * 32 + grp) * 136;
    const int rowH0 = (wr * 32 + grp) * 40;

    for (int hc = 0; hc < 8; ++hc) {
        // ===== GEMM1: H chunk [128 x 64] = X @ W1 =====
        float acc1[2][4][4];
        #pragma unroll
        for (int mi = 0; mi < 2; ++mi)
            #pragma unroll
            for (int ni = 0; ni < 4; ++ni)
                #pragma unroll
                for (int q = 0; q < 4; ++q) acc1[mi][ni][q] = 0.f;

        for (int kt = 0; kt < 8; ++kt) {       // 128 words K, slices of 16
            CP_WAIT0();
            __syncthreads();
            if (kt < 7) stage_w1(hc, kt + 1, (cur + 1) & 1);
            else        stage_w2(hc, 0, (cur + 1) & 1);
            CP_COMMIT();
            const uint32_t* Wc = Wb + (cur & 1) * 6144;
            ++cur;
            #pragma unroll
            for (int k16 = 0; k16 < 2; ++k16) {
                const int kwb = kt * 16 + k16 * 8 + 2 * tig;
                uint2 xa0 = *reinterpret_cast<const uint2*>(Xw + rowA0 + kwb);
                uint2 xa1 = *reinterpret_cast<const uint2*>(Xw + rowA0 + 8 * 136 + kwb);
                uint2 xa2 = *reinterpret_cast<const uint2*>(Xw + rowA0 + 16 * 136 + kwb);
                uint2 xa3 = *reinterpret_cast<const uint2*>(Xw + rowA0 + 24 * 136 + kwb);
                #pragma unroll
                for (int ni = 0; ni < 4; ++ni) {
                    const int nb = wc * 32 + ni * 8 + grp;
                    uint2 fb = *reinterpret_cast<const uint2*>(Wc + nb * 24 + k16 * 8 + 2 * tig);
                    mma16(acc1[0][ni], xa0.x, xa1.x, xa0.y, xa1.y, fb.x, fb.y);
                    mma16(acc1[1][ni], xa2.x, xa3.x, xa2.y, xa3.y, fb.x, fb.y);
                }
            }
        }
        // epilogue1: Hw = half2(relu(acc1 + b1)), k-permuted words
        #pragma unroll
        for (int mi = 0; mi < 2; ++mi)
            #pragma unroll
            for (int ni = 0; ni < 4; ++ni) {
                const int colg = wc * 32 + ni * 8;
                const int bcol = hc * 64 + colg + 2 * tig;
                const float bb0 = b1s[bcol], bb1 = b1s[bcol + 1];
                const int o = wc * 16 + ni * 4 + tig;          // orig word in H row
                const int pos = (o & ~7) + permpos(o & 7);
                uint32_t* h0 = Hw + rowH0 + mi * 16 * 40 + pos;
                h0[0]      = packh2(fmaxf(acc1[mi][ni][0] + bb0, 0.f),
                                    fmaxf(acc1[mi][ni][1] + bb1, 0.f));
                h0[8 * 40] = packh2(fmaxf(acc1[mi][ni][2] + bb0, 0.f),
                                    fmaxf(acc1[mi][ni][3] + bb1, 0.f));
            }
        // ===== GEMM2 partial: acc2 += Hchunk @ W2 slice =====
        for (int kt2 = 0; kt2 < 2; ++kt2) {
            CP_WAIT0();
            __syncthreads();
            if (kt2 < 1)      stage_w2(hc, 1, (cur + 1) & 1);
            else if (hc < 7)  stage_w1(hc + 1, 0, (cur + 1) & 1);
            CP_COMMIT();
            const uint32_t* Wc = Wb + (cur & 1) * 6144;
            ++cur;
            #pragma unroll
            for (int k16 = 0; k16 < 2; ++k16) {
                const int kwb = kt2 * 16 + k16 * 8 + 2 * tig;
                uint2 ha0 = *reinterpret_cast<const uint2*>(Hw + rowH0 + kwb);
                uint2 ha1 = *reinterpret_cast<const uint2*>(Hw + rowH0 + 8 * 40 + kwb);
                uint2 ha2 = *reinterpret_cast<const uint2*>(Hw + rowH0 + 16 * 40 + kwb);
                uint2 ha3 = *reinterpret_cast<const uint2*>(Hw + rowH0 + 24 * 40 + kwb);
                #pragma unroll
                for (int ni = 0; ni < 16; ++ni) {
                    const int nb = wc * 128 + ni * 8 + grp;
                    uint2 fb = *reinterpret_cast<const uint2*>(Wc + nb * 24 + k16 * 8 + 2 * tig);
                    mma16(acc2[0][ni], ha0.x, ha1.x, ha0.y, ha1.y, fb.x, fb.y);
                    mma16(acc2[1][ni], ha2.x, ha3.x, ha2.y, ha3.y, fb.x, fb.y);
                }
            }
        }
    }

    // ===== final epilogue: two 128-col halves restaged through SMEM =====
    float* Of = reinterpret_cast<float*>(smw);        // [128][132] floats, fits in Xw area
    for (int h = 0; h < 2; ++h) {
        __syncthreads();
        if (wc == h) {
            #pragma unroll
            for (int mi = 0; mi < 2; ++mi)
                #pragma unroll
                for (int ni = 0; ni < 16; ++ni) {
                    int row = wr * 32 + mi * 16 + grp;
                    int col = ni * 8 + 2 * tig;
                    Of[row * 132 + col]           = acc2[mi][ni][0];
                    Of[row * 132 + col + 1]       = acc2[mi][ni][1];
                    Of[(row + 8) * 132 + col]     = acc2[mi][ni][2];
                    Of[(row + 8) * 132 + col + 1] = acc2[mi][ni][3];
                }
        }
        __syncthreads();
        #pragma unroll 4
        for (int it = 0; it < 16; ++it) {
            int r   = it * 8 + (tid >> 5);
            int c4h = tid & 31;
            int c4  = h * 32 + c4h;
            int gr  = m0 + r;
            float4 v  = *reinterpret_cast<float4*>(Of + r * 132 + c4h * 4);
            float4 bb = *reinterpret_cast<float4*>(b2s + c4 * 4);
            v.x += bb.x; v.y += bb.y; v.z += bb.z; v.w += bb.w;
            if (EDGE) {
                int s = src[gr];
                int d = dst[gr];
                float4 nf = reinterpret_cast<const float4*>(node_feat)[s * 64 + c4];
                v.x = fmaxf(v.x + nf.x, 0.f);
                v.y = fmaxf(v.y + nf.y, 0.f);
                v.z = fmaxf(v.z + nf.z, 0.f);
                v.w = fmaxf(v.w + nf.w, 0.f);
                float* p = g_acc + (size_t)d * 256 + c4 * 4;
                asm volatile("red.global.add.v4.f32 [%0], {%1, %2, %3, %4};"
                             :: "l"(p), "f"(v.x), "f"(v.y), "f"(v.z), "f"(v.w)
                             : "memory");
            } else if (gr < M_total) {
                reinterpret_cast<float4*>(out)[gr * 64 + c4] = v;
            }
        }
    }
}

// ---------------------------------------------------------------------------
extern "C" void kernel_launch(void* const* d_in, const int* in_sizes, int n_in,
                              void* d_out, int out_size) {
    const float* node_feat = (const float*)d_in[0];
    const float* edge_feat = (const float*)d_in[1];
    const int*   src       = (const int*)d_in[2];
    const int*   dst       = (const int*)d_in[3];
    const float* We1       = (const float*)d_in[4];
    const float* be1       = (const float*)d_in[5];
    const float* We2       = (const float*)d_in[6];
    const float* be2       = (const float*)d_in[7];
    const float* Wn1       = (const float*)d_in[8];
    const float* bn1       = (const float*)d_in[9];
    const float* Wn2       = (const float*)d_in[10];
    const float* bn2       = (const float*)d_in[11];
    const float* eps       = (const float*)d_in[12];
    float* out = (float*)d_out;

    cudaFuncSetAttribute(gine_mma<true>,
                         cudaFuncAttributeMaxDynamicSharedMemorySize, SMEM_BYTES);
    cudaFuncSetAttribute(gine_mma<false>,
                         cudaFuncAttributeMaxDynamicSharedMemorySize, SMEM_BYTES);

    uint32_t *W1e, *W2e, *W1n, *W2n;
    float *accp;
    cudaGetSymbolAddress((void**)&W1e, g_W1h_e);
    cudaGetSymbolAddress((void**)&W2e, g_W2h_e);
    cudaGetSymbolAddress((void**)&W1n, g_W1h_n);
    cudaGetSymbolAddress((void**)&W2n, g_W2h_n);
    cudaGetSymbolAddress((void**)&accp, g_acc);

    // 1) fused: acc = (1+eps)*node_feat  +  all 4 weight conversions
    prep_kernel<<<6024, 256>>>(node_feat, eps, We1, We2, Wn1, Wn2);

    // 2) edge MLP + gather/relu/scatter-add  (2500 CTAs)
    gine_mma<true><<<N_EDGES / 128, 256, SMEM_BYTES>>>(
        edge_feat, W1e, be1, W2e, be2, node_feat, src, dst, nullptr, N_EDGES);

    // 3) node MLP on acc -> out              (157 CTAs)
    gine_mma<false><<<(N_NODES + 127) / 128, 256, SMEM_BYTES>>>(
        accp, W1n, bn1, W2n, bn2, nullptr, nullptr, nullptr, out, N_NODES);

    // 4) alignment dummy so ncu (-s 5 -c 1) lands on the edge kernel
    noop_kernel<<<1, 1>>>();
}